// round 1
// baseline (speedup 1.0000x reference)
#include <cuda_runtime.h>
#include <cstdint>

// Problem constants
#define BB   4
#define TT   2048
#define NN   4
#define CC   1024
#define NC   4096      // N*C
#define AA   8
#define KTOT 24        // 4 pre + 4 post + 16 res
#define SINK_ITERS 20
#define EPS_ 1e-5f

// Phase-1 tiling
#define TOK  32        // tokens per CTA
#define DT   128       // d-tile
#define XROW 132       // x smem row stride (floats), 33 float4

// ---------------- scratch (device globals; no runtime allocation) ----------------
__device__ __align__(16) float g_buf[AA * NC * KTOT];   // folded alpha*w*phi, [A][4096][24]
__device__ __align__(16) float W_buf[BB * TT * 16];     // per-token 4x4 combined matrix

// ---------------- f32x2 helpers ----------------
__device__ __forceinline__ void ffma2(unsigned long long& d, unsigned long long a, unsigned long long b) {
    asm("fma.rn.f32x2 %0, %1, %2, %0;" : "+l"(d) : "l"(a), "l"(b));
}
__device__ __forceinline__ void fadd2(unsigned long long& d, unsigned long long a, unsigned long long b) {
    asm("add.rn.f32x2 %0, %1, %2;" : "=l"(d) : "l"(a), "l"(b));
}
__device__ __forceinline__ unsigned long long pack2(float lo, float hi) {
    unsigned long long r; asm("mov.b64 %0, {%1, %2};" : "=l"(r) : "f"(lo), "f"(hi)); return r;
}
__device__ __forceinline__ unsigned long long dup2(float v) {
    unsigned long long r; asm("mov.b64 %0, {%1, %1};" : "=l"(r) : "f"(v)); return r;
}
__device__ __forceinline__ void unpack2(unsigned long long u, float& lo, float& hi) {
    asm("mov.b64 {%0, %1}, %2;" : "=f"(lo), "=f"(hi) : "l"(u));
}

// ---------------- kernel 1: fold alpha * w * phi into g_buf ----------------
__global__ void fold_k(const float* __restrict__ w,
                       const float* __restrict__ ppre, const float* __restrict__ ppost,
                       const float* __restrict__ pres,
                       const float* __restrict__ apre, const float* __restrict__ apost,
                       const float* __restrict__ ares) {
    int i = blockIdx.x * blockDim.x + threadIdx.x;   // a*4096 + d
    if (i >= AA * NC) return;
    int a = i >> 12;
    float wv = w[i];
    float cp = apre[a] * wv, cq = apost[a] * wv, cr = ares[a] * wv;
    float4* dst = (float4*)(g_buf + (size_t)i * KTOT);   // 24 floats, 16B-aligned (96B stride)
    float4 v;
    v = ((const float4*)ppre)[i];
    dst[0] = make_float4(cp * v.x, cp * v.y, cp * v.z, cp * v.w);
    v = ((const float4*)ppost)[i];
    dst[1] = make_float4(cq * v.x, cq * v.y, cq * v.z, cq * v.w);
    const float4* r = (const float4*)pres + (size_t)i * 4;
#pragma unroll
    for (int q = 0; q < 4; ++q) {
        v = r[q];
        dst[2 + q] = make_float4(cr * v.x, cr * v.y, cr * v.z, cr * v.w);
    }
}

// ---------------- kernel 2: logits + sinkhorn -> W per token ----------------
// Block: 128 threads. thread = (pair p in 0..15, slice s in 0..7).
// Each thread accumulates packed (token 2p, 2p+1) x 24 logits over d = s, s+8, ...
__global__ void __launch_bounds__(128, 4)
logits_k(const float* __restrict__ x,
         const float* __restrict__ bpre, const float* __restrict__ bpost,
         const float* __restrict__ bres, const int* __restrict__ aidx) {
    __shared__ float sxf[TOK * XROW];                 // [tok][132]  16.9 KB
    __shared__ ulonglong2 sphi[DT * 13];              // [d][12] pairs of dup'd phi, 208B row, 26.6 KB

    const int tid = threadIdx.x;
    const int b  = blockIdx.x >> 6;                   // 64 tiles per batch
    const int t0 = (blockIdx.x & 63) * TOK;
    const int aid = aidx[b];
    const int p = tid >> 3, s = tid & 7;

    unsigned long long acc[KTOT];
#pragma unroll
    for (int k = 0; k < KTOT; ++k) acc[k] = 0ull;
    unsigned long long ssq = 0ull;

    const float* xb = x + ((size_t)(b * TT + t0)) * NC;
    const float* gb = g_buf + (size_t)aid * NC * KTOT;
    float4* sxf4 = (float4*)sxf;
    const float* xlo = sxf + (2 * p) * XROW;
    const float* xhi = xlo + XROW;

    for (int tile = 0; tile < NC / DT; ++tile) {
        const int d0 = tile * DT;
        __syncthreads();
        // x tile: 32 tok x 128 d = 1024 float4, coalesced load, STS.128 conflict-free
#pragma unroll
        for (int i = 0; i < 8; ++i) {
            int f = i * 128 + tid;
            int tok = f >> 5, q = f & 31;
            float4 v = *(const float4*)(xb + (size_t)tok * NC + d0 + q * 4);
            sxf4[tok * 33 + q] = v;
        }
        // phi tile: 128 d x 24 = 768 float4; duplicate each scalar into f32x2 pairs
#pragma unroll
        for (int i = 0; i < 6; ++i) {
            int f = i * 128 + tid;
            int d = f / 6, k4 = f - d * 6;
            float4 v = *(const float4*)(gb + (size_t)(d0 + d) * KTOT + k4 * 4);
            ulonglong2 u0; u0.x = dup2(v.x); u0.y = dup2(v.y);
            ulonglong2 u1; u1.x = dup2(v.z); u1.y = dup2(v.w);
            sphi[d * 13 + k4 * 2]     = u0;
            sphi[d * 13 + k4 * 2 + 1] = u1;
        }
        __syncthreads();
        // compute: per d, pack 2 tokens, 24 FFMA2 (+sumsq)
        for (int dd = s; dd < DT; dd += 8) {
            unsigned long long x2 = pack2(xlo[dd], xhi[dd]);
            ffma2(ssq, x2, x2);
            const ulonglong2* ph = sphi + dd * 13;
#pragma unroll
            for (int kk = 0; kk < 12; ++kk) {
                ulonglong2 t = ph[kk];
                ffma2(acc[2 * kk],     x2, t.x);
                ffma2(acc[2 * kk + 1], x2, t.y);
            }
        }
    }

    // butterfly reduce over the 8 d-slices (lane bits 0..2)
#pragma unroll
    for (int k = 0; k < KTOT; ++k) {
#pragma unroll
        for (int m = 1; m < 8; m <<= 1) {
            unsigned long long o = __shfl_xor_sync(0xffffffffu, acc[k], m);
            fadd2(acc[k], acc[k], o);
        }
    }
#pragma unroll
    for (int m = 1; m < 8; m <<= 1) {
        unsigned long long o = __shfl_xor_sync(0xffffffffu, ssq, m);
        fadd2(ssq, ssq, o);
    }

    // s==0 handles token 2p, s==1 handles token 2p+1
    if (s < 2) {
        float a[KTOT];
#pragma unroll
        for (int k = 0; k < KTOT; ++k) {
            float lo, hi; unpack2(acc[k], lo, hi);
            a[k] = s ? hi : lo;
        }
        float slo, shi; unpack2(ssq, slo, shi);
        float sq = s ? shi : slo;
        float rinv = rsqrtf(sq * (1.0f / 4096.0f) + EPS_);

        float hpre[4], hpost[4];
#pragma unroll
        for (int n = 0; n < 4; ++n)
            hpre[n] = 1.0f / (1.0f + expf(-(a[n] * rinv + bpre[aid * 4 + n])));
#pragma unroll
        for (int n = 0; n < 4; ++n)
            hpost[n] = 2.0f / (1.0f + expf(-(a[4 + n] * rinv + bpost[aid * 4 + n])));

        float m[16];
#pragma unroll
        for (int ij = 0; ij < 16; ++ij)
            m[ij] = expf(a[8 + ij] * rinv + bres[aid * 16 + ij]);

        // Sinkhorn-Knopp: row normalize then column normalize, 20 iterations
        for (int it = 0; it < SINK_ITERS; ++it) {
#pragma unroll
            for (int i = 0; i < 4; ++i) {
                float rs = m[i * 4] + m[i * 4 + 1] + m[i * 4 + 2] + m[i * 4 + 3];
                float r = 1.0f / rs;
                m[i * 4] *= r; m[i * 4 + 1] *= r; m[i * 4 + 2] *= r; m[i * 4 + 3] *= r;
            }
#pragma unroll
            for (int j = 0; j < 4; ++j) {
                float cs = m[j] + m[4 + j] + m[8 + j] + m[12 + j];
                float r = 1.0f / cs;
                m[j] *= r; m[4 + j] *= r; m[8 + j] *= r; m[12 + j] *= r;
            }
        }

        const int tg = b * TT + t0 + 2 * p + s;
        float* wd = W_buf + (size_t)tg * 16;
#pragma unroll
        for (int i = 0; i < 4; ++i)
#pragma unroll
            for (int j = 0; j < 4; ++j)
                wd[i * 4 + j] = m[i * 4 + j] + hpost[i] * hpre[j];
    }
}

// ---------------- kernel 3: out[token] = W @ x[token]  (streaming, HBM-bound) ----------------
__global__ void out_k(const float* __restrict__ x, float* __restrict__ out) {
    const int token = blockIdx.x;
    __shared__ float sW[16];
    if (threadIdx.x < 16) sW[threadIdx.x] = W_buf[(size_t)token * 16 + threadIdx.x];
    __syncthreads();
    const float4* xr = (const float4*)(x + (size_t)token * NC);
    float4* orow = (float4*)(out + (size_t)token * NC);
    const int c = threadIdx.x;   // 0..255, covers C=1024 as float4
    float4 xv0 = xr[c], xv1 = xr[256 + c], xv2 = xr[512 + c], xv3 = xr[768 + c];
#pragma unroll
    for (int i = 0; i < 4; ++i) {
        float w0 = sW[i * 4], w1 = sW[i * 4 + 1], w2 = sW[i * 4 + 2], w3 = sW[i * 4 + 3];
        float4 o;
        o.x = w0 * xv0.x + w1 * xv1.x + w2 * xv2.x + w3 * xv3.x;
        o.y = w0 * xv0.y + w1 * xv1.y + w2 * xv2.y + w3 * xv3.y;
        o.z = w0 * xv0.z + w1 * xv1.z + w2 * xv2.z + w3 * xv3.z;
        o.w = w0 * xv0.w + w1 * xv1.w + w2 * xv2.w + w3 * xv3.w;
        orow[i * 256 + c] = o;
    }
}

// ---------------- launch ----------------
extern "C" void kernel_launch(void* const* d_in, const int* in_sizes, int n_in,
                              void* d_out, int out_size) {
    const float* x     = (const float*)d_in[0];
    const float* wnorm = (const float*)d_in[1];
    const float* ppre  = (const float*)d_in[2];
    const float* ppost = (const float*)d_in[3];
    const float* pres  = (const float*)d_in[4];
    const float* bpre  = (const float*)d_in[5];
    const float* bpost = (const float*)d_in[6];
    const float* bres  = (const float*)d_in[7];
    const float* apre  = (const float*)d_in[8];
    const float* apost = (const float*)d_in[9];
    const float* ares  = (const float*)d_in[10];
    const int*   aidx  = (const int*)d_in[11];
    float* out = (float*)d_out;

    fold_k<<<(AA * NC + 127) / 128, 128>>>(wnorm, ppre, ppost, pres, apre, apost, ares);
    logits_k<<<(BB * TT) / TOK, 128>>>(x, bpre, bpost, bres, aidx);
    out_k<<<BB * TT, 256>>>(x, out);
}

// round 2
// speedup vs baseline: 1.9730x; 1.9730x over previous
#include <cuda_runtime.h>
#include <cstdint>

// Problem constants
#define BB   4
#define TT   2048
#define NC   4096
#define AA   8
#define KTOT 24        // 4 pre + 4 post + 16 res
#define SINK_ITERS 20
#define EPS_ 1e-5f

#define TOK    32      // tokens per CTA
#define DT     128     // d-tile
#define KSPLIT 4       // K split: each logits CTA handles NC/KSPLIT = 1024 d
#define DPART  (NC / KSPLIT)
#define XROW   132     // x smem row stride (floats)
#define PROW   28      // phi smem row stride (floats)
#define PARTW  28      // partial row width: 24 logits + ssq + pad

// ---------------- scratch (device globals) ----------------
__device__ __align__(16) float part_buf[KSPLIT * BB * TT * PARTW];  // 3.67 MB
__device__ __align__(16) float W_buf[BB * TT * 16];

// ---------------- f32x2 helpers ----------------
typedef unsigned long long ull;
__device__ __forceinline__ void ffma2(ull& d, ull a, ull b) {
    asm("fma.rn.f32x2 %0, %1, %2, %0;" : "+l"(d) : "l"(a), "l"(b));
}
__device__ __forceinline__ void fadd2(ull& d, ull a, ull b) {
    asm("add.rn.f32x2 %0, %1, %2;" : "=l"(d) : "l"(a), "l"(b));
}
__device__ __forceinline__ ull pack2(float lo, float hi) {
    ull r; asm("mov.b64 %0, {%1, %2};" : "=l"(r) : "f"(lo), "f"(hi)); return r;
}
__device__ __forceinline__ ull dup2(float v) {
    ull r; asm("mov.b64 %0, {%1, %1};" : "=l"(r) : "f"(v)); return r;
}
__device__ __forceinline__ void unpack2(ull u, float& lo, float& hi) {
    asm("mov.b64 {%0, %1}, %2;" : "=f"(lo), "=f"(hi) : "l"(u));
}

// ---------------- kernel 1: partial logits (fold fused into phi load) ----------------
// grid = 1024: blockIdx.x = token_tile*KSPLIT + ks. 128 threads:
//   s  = tid & 7   : d-slice within tile
//   pg = (tid>>3)&7: handles token pairs pg (tok 2pg,2pg+1) and pg+8 (tok 2pg+16,2pg+17)
//   kh = tid>>6    : k half (k = kh*12 .. kh*12+11)
__global__ void __launch_bounds__(128, 4)
logits_k(const float* __restrict__ x,
         const float* __restrict__ wnorm,
         const float* __restrict__ ppre, const float* __restrict__ ppost,
         const float* __restrict__ pres,
         const float* __restrict__ apre, const float* __restrict__ apost,
         const float* __restrict__ ares,
         const int* __restrict__ aidx) {
    __shared__ float sx[TOK * XROW];     // 16.9 KB
    __shared__ float sp[DT * PROW];      // 14.3 KB

    const int tid = threadIdx.x;
    const int ks = blockIdx.x & (KSPLIT - 1);
    const int tt = blockIdx.x / KSPLIT;
    const int b  = tt >> 6;
    const int t0 = (tt & 63) * TOK;
    const int aid = aidx[b];
    const int s = tid & 7, pg = (tid >> 3) & 7, kh = tid >> 6;

    const float av_pre  = apre[aid];
    const float av_post = apost[aid];
    const float av_res  = ares[aid];

    ull acc[24];
#pragma unroll
    for (int k = 0; k < 24; ++k) acc[k] = 0ull;
    ull ssqa = 0ull, ssqb = 0ull;

    const float* xb = x + ((size_t)(b * TT + t0)) * NC + ks * DPART;
    const size_t dbase = (size_t)aid * NC + ks * DPART;

    float4* sx4 = (float4*)sx;
    float4* sp4 = (float4*)sp;

    for (int tile = 0; tile < DPART / DT; ++tile) {
        const int d0 = tile * DT;
        __syncthreads();
        // x tile: 32 tok x 128 d = 1024 float4
#pragma unroll
        for (int i = 0; i < 8; ++i) {
            int f = i * 128 + tid;
            int tok = f >> 5, q = f & 31;
            sx4[tok * 33 + q] = *(const float4*)(xb + (size_t)tok * NC + d0 + q * 4);
        }
        // phi tile with fold: 128 d x 6 float4 (24 k). c=0 pre, c=1 post, c=2..5 res.
#pragma unroll
        for (int i = 0; i < 6; ++i) {
            int f = i * 128 + tid;
            int d = f / 6, c = f - d * 6;
            size_t dg = dbase + d0 + d;
            float wv = wnorm[dg];
            float coef = ((c == 0) ? av_pre : (c == 1) ? av_post : av_res) * wv;
            const float4* src = (c == 0) ? (const float4*)(ppre + dg * 4)
                              : (c == 1) ? (const float4*)(ppost + dg * 4)
                                         : (const float4*)(pres + dg * 16 + (size_t)(c - 2) * 4);
            float4 v = *src;
            sp4[d * 7 + c] = make_float4(coef * v.x, coef * v.y, coef * v.z, coef * v.w);
        }
        __syncthreads();
#pragma unroll 4
        for (int i = 0; i < 16; ++i) {
            const int dd = i * 8 + s;
            ull x2a = pack2(sx[(2 * pg) * XROW + dd],      sx[(2 * pg + 1) * XROW + dd]);
            ull x2b = pack2(sx[(2 * pg + 16) * XROW + dd], sx[(2 * pg + 17) * XROW + dd]);
            if (kh == 0) { ffma2(ssqa, x2a, x2a); ffma2(ssqb, x2b, x2b); }
            const float4* pb = (const float4*)(sp + dd * PROW + kh * 12);
            float4 p0 = pb[0], p1 = pb[1], p2 = pb[2];
            ull t;
            t = dup2(p0.x); ffma2(acc[0],  x2a, t); ffma2(acc[12], x2b, t);
            t = dup2(p0.y); ffma2(acc[1],  x2a, t); ffma2(acc[13], x2b, t);
            t = dup2(p0.z); ffma2(acc[2],  x2a, t); ffma2(acc[14], x2b, t);
            t = dup2(p0.w); ffma2(acc[3],  x2a, t); ffma2(acc[15], x2b, t);
            t = dup2(p1.x); ffma2(acc[4],  x2a, t); ffma2(acc[16], x2b, t);
            t = dup2(p1.y); ffma2(acc[5],  x2a, t); ffma2(acc[17], x2b, t);
            t = dup2(p1.z); ffma2(acc[6],  x2a, t); ffma2(acc[18], x2b, t);
            t = dup2(p1.w); ffma2(acc[7],  x2a, t); ffma2(acc[19], x2b, t);
            t = dup2(p2.x); ffma2(acc[8],  x2a, t); ffma2(acc[20], x2b, t);
            t = dup2(p2.y); ffma2(acc[9],  x2a, t); ffma2(acc[21], x2b, t);
            t = dup2(p2.z); ffma2(acc[10], x2a, t); ffma2(acc[22], x2b, t);
            t = dup2(p2.w); ffma2(acc[11], x2a, t); ffma2(acc[23], x2b, t);
        }
    }

    // reduce over the 8 d-slices (lane bits 0..2)
#pragma unroll
    for (int k = 0; k < 24; ++k) {
#pragma unroll
        for (int m = 1; m < 8; m <<= 1) {
            ull o = __shfl_xor_sync(0xffffffffu, acc[k], m);
            fadd2(acc[k], acc[k], o);
        }
    }
#pragma unroll
    for (int m = 1; m < 8; m <<= 1) {
        ull oa = __shfl_xor_sync(0xffffffffu, ssqa, m);
        fadd2(ssqa, ssqa, oa);
        ull ob = __shfl_xor_sync(0xffffffffu, ssqb, m);
        fadd2(ssqb, ssqb, ob);
    }

    if (s < 2) {
        const int gta = b * TT + t0 + 2 * pg + s;        // token for pair a
        const int gtb = gta + 16;                        // token for pair b
        float* pa = part_buf + ((size_t)ks * (BB * TT) + gta) * PARTW;
        float* pb = part_buf + ((size_t)ks * (BB * TT) + gtb) * PARTW;
#pragma unroll
        for (int j = 0; j < 12; ++j) {
            float lo, hi;
            unpack2(acc[j], lo, hi);
            pa[kh * 12 + j] = s ? hi : lo;
            unpack2(acc[12 + j], lo, hi);
            pb[kh * 12 + j] = s ? hi : lo;
        }
        if (kh == 0) {
            float lo, hi;
            unpack2(ssqa, lo, hi);
            pa[24] = s ? hi : lo;
            unpack2(ssqb, lo, hi);
            pb[24] = s ? hi : lo;
        }
    }
}

// ---------------- kernel 2: finalize (reduce splits, sinkhorn -> W) ----------------
__global__ void finalize_k(const float* __restrict__ bpre, const float* __restrict__ bpost,
                           const float* __restrict__ bres, const int* __restrict__ aidx) {
    const int t = blockIdx.x * 128 + threadIdx.x;    // 0..8191
    const int aid = aidx[t >> 11];

    float a[24];
#pragma unroll
    for (int k = 0; k < 24; ++k) a[k] = 0.0f;
    float ssq = 0.0f;
#pragma unroll
    for (int ks = 0; ks < KSPLIT; ++ks) {
        const float4* p = (const float4*)(part_buf + ((size_t)ks * (BB * TT) + t) * PARTW);
#pragma unroll
        for (int q = 0; q < 6; ++q) {
            float4 v = p[q];
            a[q * 4 + 0] += v.x; a[q * 4 + 1] += v.y;
            a[q * 4 + 2] += v.z; a[q * 4 + 3] += v.w;
        }
        ssq += p[6].x;
    }
    float rinv = rsqrtf(ssq * (1.0f / 4096.0f) + EPS_);

    float hpre[4], hpost[4];
#pragma unroll
    for (int n = 0; n < 4; ++n)
        hpre[n] = 1.0f / (1.0f + expf(-(a[n] * rinv + bpre[aid * 4 + n])));
#pragma unroll
    for (int n = 0; n < 4; ++n)
        hpost[n] = 2.0f / (1.0f + expf(-(a[4 + n] * rinv + bpost[aid * 4 + n])));

    float m[16];
#pragma unroll
    for (int ij = 0; ij < 16; ++ij)
        m[ij] = expf(a[8 + ij] * rinv + bres[aid * 16 + ij]);

    for (int it = 0; it < SINK_ITERS; ++it) {
#pragma unroll
        for (int i = 0; i < 4; ++i) {
            float r = 1.0f / (m[i * 4] + m[i * 4 + 1] + m[i * 4 + 2] + m[i * 4 + 3]);
            m[i * 4] *= r; m[i * 4 + 1] *= r; m[i * 4 + 2] *= r; m[i * 4 + 3] *= r;
        }
#pragma unroll
        for (int j = 0; j < 4; ++j) {
            float r = 1.0f / (m[j] + m[4 + j] + m[8 + j] + m[12 + j]);
            m[j] *= r; m[4 + j] *= r; m[8 + j] *= r; m[12 + j] *= r;
        }
    }

    float4* wd = (float4*)(W_buf + (size_t)t * 16);
#pragma unroll
    for (int i = 0; i < 4; ++i)
        wd[i] = make_float4(m[i * 4 + 0] + hpost[i] * hpre[0],
                            m[i * 4 + 1] + hpost[i] * hpre[1],
                            m[i * 4 + 2] + hpost[i] * hpre[2],
                            m[i * 4 + 3] + hpost[i] * hpre[3]);
}

// ---------------- kernel 3: out[token] = W @ x[token] ----------------
__global__ void out_k(const float* __restrict__ x, float* __restrict__ out) {
    const int token = blockIdx.x;
    __shared__ float sW[16];
    if (threadIdx.x < 16) sW[threadIdx.x] = W_buf[(size_t)token * 16 + threadIdx.x];
    __syncthreads();
    const float4* xr = (const float4*)(x + (size_t)token * NC);
    float4* orow = (float4*)(out + (size_t)token * NC);
    const int c = threadIdx.x;   // 0..255
    float4 xv0 = xr[c], xv1 = xr[256 + c], xv2 = xr[512 + c], xv3 = xr[768 + c];
#pragma unroll
    for (int i = 0; i < 4; ++i) {
        float w0 = sW[i * 4], w1 = sW[i * 4 + 1], w2 = sW[i * 4 + 2], w3 = sW[i * 4 + 3];
        float4 o;
        o.x = w0 * xv0.x + w1 * xv1.x + w2 * xv2.x + w3 * xv3.x;
        o.y = w0 * xv0.y + w1 * xv1.y + w2 * xv2.y + w3 * xv3.y;
        o.z = w0 * xv0.z + w1 * xv1.z + w2 * xv2.z + w3 * xv3.z;
        o.w = w0 * xv0.w + w1 * xv1.w + w2 * xv2.w + w3 * xv3.w;
        orow[i * 256 + c] = o;
    }
}

// ---------------- launch ----------------
extern "C" void kernel_launch(void* const* d_in, const int* in_sizes, int n_in,
                              void* d_out, int out_size) {
    const float* x     = (const float*)d_in[0];
    const float* wnorm = (const float*)d_in[1];
    const float* ppre  = (const float*)d_in[2];
    const float* ppost = (const float*)d_in[3];
    const float* pres  = (const float*)d_in[4];
    const float* bpre  = (const float*)d_in[5];
    const float* bpost = (const float*)d_in[6];
    const float* bres  = (const float*)d_in[7];
    const float* apre  = (const float*)d_in[8];
    const float* apost = (const float*)d_in[9];
    const float* ares  = (const float*)d_in[10];
    const int*   aidx  = (const int*)d_in[11];
    float* out = (float*)d_out;

    logits_k<<<(BB * TT / TOK) * KSPLIT, 128>>>(x, wnorm, ppre, ppost, pres,
                                                apre, apost, ares, aidx);
    finalize_k<<<BB * TT / 128, 128>>>(bpre, bpost, bres, aidx);
    out_k<<<BB * TT, 256>>>(x, out);
}

// round 3
// speedup vs baseline: 2.7171x; 1.3771x over previous
#include <cuda_runtime.h>
#include <cstdint>

// Problem constants
#define BB   4
#define TT   2048
#define NC   4096
#define AA   8
#define SINK_ITERS 20
#define EPS_ 1e-5f

#define TOK    32            // tokens per CTA
#define DT     128           // d-tile
#define KSPLIT 8
#define DPART  (NC / KSPLIT) // 512
#define TILES  (DPART / DT)  // 4
#define XROWF  136           // x smem row stride (floats): bank = (8*tg+s), conflict-free
#define PROWF  28            // phi smem row stride (floats): 7 float4, odd -> conflict-free
#define PARTW  28            // partial row: 24 logits + ssq + pad

#define XT (TOK * XROWF)     // 4352 floats
#define PT (DT * PROWF)      // 3584 floats
#define BUFF (XT + PT)       // 7936 floats = 31744 B
#define SMEM_BYTES (2 * BUFF * 4)

// ---------------- scratch ----------------
__device__ __align__(16) float g_buf[AA * NC * 24];                 // folded phi [A][4096][24]
__device__ __align__(16) float part_buf[KSPLIT * BB * TT * PARTW];  // 7.3 MB
__device__ __align__(16) float W_buf[BB * TT * 16];

// ---------------- helpers ----------------
typedef unsigned long long ull;
__device__ __forceinline__ void ffma2(ull& d, ull a, ull b) {
    asm("fma.rn.f32x2 %0, %1, %2, %0;" : "+l"(d) : "l"(a), "l"(b));
}
__device__ __forceinline__ void fadd2(ull& d, ull a, ull b) {
    asm("add.rn.f32x2 %0, %1, %2;" : "=l"(d) : "l"(a), "l"(b));
}
__device__ __forceinline__ ull dup2(float v) {
    ull r; asm("mov.b64 %0, {%1, %1};" : "=l"(r) : "f"(v)); return r;
}
__device__ __forceinline__ void unpack2(ull u, float& lo, float& hi) {
    asm("mov.b64 {%0, %1}, %2;" : "=f"(lo), "=f"(hi) : "l"(u));
}
__device__ __forceinline__ void cp16(uint32_t dst, const void* src) {
    asm volatile("cp.async.cg.shared.global [%0], [%1], 16;" :: "r"(dst), "l"(src));
}
__device__ __forceinline__ void cp_commit() {
    asm volatile("cp.async.commit_group;");
}

// ---------------- kernel 1: fold alpha*w*phi -> g_buf[a][d][24] ----------------
__global__ void fold_k(const float* __restrict__ wnorm,
                       const float* __restrict__ ppre, const float* __restrict__ ppost,
                       const float* __restrict__ pres,
                       const float* __restrict__ apre, const float* __restrict__ apost,
                       const float* __restrict__ ares) {
    int idx = blockIdx.x * 256 + threadIdx.x;       // (a,d,c): ad*6 + c
    if (idx >= AA * NC * 6) return;
    int c = idx % 6;
    int ad = idx / 6;
    int a = ad >> 12;
    float wv = wnorm[ad];
    float coef = ((c == 0) ? apre[a] : (c == 1) ? apost[a] : ares[a]) * wv;
    float4 v = (c == 0) ? ((const float4*)ppre)[ad]
             : (c == 1) ? ((const float4*)ppost)[ad]
                        : ((const float4*)pres)[(size_t)ad * 4 + (c - 2)];
    ((float4*)g_buf)[idx] = make_float4(coef * v.x, coef * v.y, coef * v.z, coef * v.w);
}

// ---------------- kernel 2: partial logits, cp.async double-buffered ----------------
// grid = 2048: blockIdx.x = tt*KSPLIT + ks. 128 threads:
//   s = tid&7 (d-slice), tg = (tid>>3)&7 (token group: tokens tg+8j), kh = tid>>6 (k half)
// acc[j][c] : f32x2 over k-pair (kh*12+2c, kh*12+2c+1) for token tg+8j
__global__ void __launch_bounds__(128, 3)
logits_k(const float* __restrict__ x, const int* __restrict__ aidx) {
    extern __shared__ float smem[];
    const int tid = threadIdx.x;
    const int ks = blockIdx.x & (KSPLIT - 1);
    const int tt = blockIdx.x >> 3;
    const int b  = tt >> 6;
    const int t0 = (tt & 63) * TOK;
    const int aid = aidx[b];
    const int s = tid & 7, tg = (tid >> 3) & 7, kh = tid >> 6;

    const float* xb = x + ((size_t)(b * TT + t0)) * NC + ks * DPART;
    const float* gb = g_buf + ((size_t)aid * NC + ks * DPART) * 24;

    uint32_t sbase = (uint32_t)__cvta_generic_to_shared(smem);
    const uint32_t xbase[2] = { sbase,                 sbase + BUFF * 4 };
    const uint32_t pbase[2] = { sbase + XT * 4,        sbase + (BUFF + XT) * 4 };

    ull acc[24];
#pragma unroll
    for (int k = 0; k < 24; ++k) acc[k] = 0ull;
    ull ssq[4] = {0ull, 0ull, 0ull, 0ull};

    // ---- async tile copy ----
    auto copy_tile = [&](int tile, int bi) {
        const int d0 = tile * DT;
#pragma unroll
        for (int i2 = 0; i2 < 8; ++i2) {            // x: 1024 float4
            int f = i2 * 128 + tid;
            int tok = f >> 5, q = f & 31;
            cp16(xbase[bi] + tok * (XROWF * 4) + q * 16,
                 xb + (size_t)tok * NC + d0 + q * 4);
        }
#pragma unroll
        for (int i2 = 0; i2 < 6; ++i2) {            // phi: 768 float4
            int f = i2 * 128 + tid;
            int d = f / 6, c = f - d * 6;
            cp16(pbase[bi] + d * (PROWF * 4) + c * 16,
                 gb + (size_t)(d0 + d) * 24 + c * 4);
        }
        cp_commit();
    };

    copy_tile(0, 0);

    for (int t = 0; t < TILES; ++t) {
        if (t + 1 < TILES) {
            copy_tile(t + 1, (t + 1) & 1);
            asm volatile("cp.async.wait_group 1;");
        } else {
            asm volatile("cp.async.wait_group 0;");
        }
        __syncthreads();

        const float* xs = smem + (t & 1) * BUFF;
        const float* ps = smem + (t & 1) * BUFF + XT;
        const float* xr0 = xs + (tg    ) * XROWF;
        const float* xr1 = xs + (tg + 8) * XROWF;
        const float* xr2 = xs + (tg + 16) * XROWF;
        const float* xr3 = xs + (tg + 24) * XROWF;

#pragma unroll 4
        for (int i = 0; i < 16; ++i) {
            const int dd = i * 8 + s;
            ull x0 = dup2(xr0[dd]);
            ull x1 = dup2(xr1[dd]);
            ull x2 = dup2(xr2[dd]);
            ull x3 = dup2(xr3[dd]);
            if (kh == 0) {
                ffma2(ssq[0], x0, x0); ffma2(ssq[1], x1, x1);
                ffma2(ssq[2], x2, x2); ffma2(ssq[3], x3, x3);
            }
            const ulonglong2* pp = (const ulonglong2*)(ps + dd * PROWF + kh * 12);
            ulonglong2 pA = pp[0], pB = pp[1], pC = pp[2];
            ffma2(acc[0],  x0, pA.x); ffma2(acc[6],  x1, pA.x);
            ffma2(acc[12], x2, pA.x); ffma2(acc[18], x3, pA.x);
            ffma2(acc[1],  x0, pA.y); ffma2(acc[7],  x1, pA.y);
            ffma2(acc[13], x2, pA.y); ffma2(acc[19], x3, pA.y);
            ffma2(acc[2],  x0, pB.x); ffma2(acc[8],  x1, pB.x);
            ffma2(acc[14], x2, pB.x); ffma2(acc[20], x3, pB.x);
            ffma2(acc[3],  x0, pB.y); ffma2(acc[9],  x1, pB.y);
            ffma2(acc[15], x2, pB.y); ffma2(acc[21], x3, pB.y);
            ffma2(acc[4],  x0, pC.x); ffma2(acc[10], x1, pC.x);
            ffma2(acc[16], x2, pC.x); ffma2(acc[22], x3, pC.x);
            ffma2(acc[5],  x0, pC.y); ffma2(acc[11], x1, pC.y);
            ffma2(acc[17], x2, pC.y); ffma2(acc[23], x3, pC.y);
        }
        __syncthreads();
    }

    // reduce over the 8 d-slices (lane bits 0..2)
#pragma unroll
    for (int k = 0; k < 24; ++k) {
#pragma unroll
        for (int m = 1; m < 8; m <<= 1) {
            ull o = __shfl_xor_sync(0xffffffffu, acc[k], m);
            fadd2(acc[k], acc[k], o);
        }
    }
    if (kh == 0) {
#pragma unroll
        for (int j = 0; j < 4; ++j) {
#pragma unroll
            for (int m = 1; m < 8; m <<= 1) {
                ull o = __shfl_xor_sync(0xffffffffu, ssq[j], m);
                fadd2(ssq[j], ssq[j], o);
            }
        }
    }

    if (s == 0) {
        const int tbase = b * TT + t0 + tg;
#pragma unroll
        for (int j = 0; j < 4; ++j) {
            float* pa = part_buf + ((size_t)ks * (BB * TT) + tbase + 8 * j) * PARTW;
#pragma unroll
            for (int c = 0; c < 6; ++c) {
                float lo, hi; unpack2(acc[j * 6 + c], lo, hi);
                pa[kh * 12 + 2 * c]     = lo;
                pa[kh * 12 + 2 * c + 1] = hi;
            }
            if (kh == 0) {
                float lo, hi; unpack2(ssq[j], lo, hi);
                pa[24] = lo;
            }
        }
    }
}

// ---------------- kernel 3: finalize (reduce splits, sinkhorn -> W) ----------------
__global__ void finalize_k(const float* __restrict__ bpre, const float* __restrict__ bpost,
                           const float* __restrict__ bres, const int* __restrict__ aidx) {
    const int t = blockIdx.x * 128 + threadIdx.x;
    const int aid = aidx[t >> 11];

    float a[24];
#pragma unroll
    for (int k = 0; k < 24; ++k) a[k] = 0.0f;
    float ssq = 0.0f;
#pragma unroll
    for (int ks = 0; ks < KSPLIT; ++ks) {
        const float4* p = (const float4*)(part_buf + ((size_t)ks * (BB * TT) + t) * PARTW);
#pragma unroll
        for (int q = 0; q < 6; ++q) {
            float4 v = p[q];
            a[q * 4 + 0] += v.x; a[q * 4 + 1] += v.y;
            a[q * 4 + 2] += v.z; a[q * 4 + 3] += v.w;
        }
        ssq += p[6].x;
    }
    float rinv = rsqrtf(ssq * (1.0f / 4096.0f) + EPS_);

    float hpre[4], hpost[4];
#pragma unroll
    for (int n = 0; n < 4; ++n)
        hpre[n] = 1.0f / (1.0f + expf(-(a[n] * rinv + bpre[aid * 4 + n])));
#pragma unroll
    for (int n = 0; n < 4; ++n)
        hpost[n] = 2.0f / (1.0f + expf(-(a[4 + n] * rinv + bpost[aid * 4 + n])));

    float m[16];
#pragma unroll
    for (int ij = 0; ij < 16; ++ij)
        m[ij] = expf(a[8 + ij] * rinv + bres[aid * 16 + ij]);

    for (int it = 0; it < SINK_ITERS; ++it) {
#pragma unroll
        for (int i = 0; i < 4; ++i) {
            float r = 1.0f / (m[i * 4] + m[i * 4 + 1] + m[i * 4 + 2] + m[i * 4 + 3]);
            m[i * 4] *= r; m[i * 4 + 1] *= r; m[i * 4 + 2] *= r; m[i * 4 + 3] *= r;
        }
#pragma unroll
        for (int j = 0; j < 4; ++j) {
            float r = 1.0f / (m[j] + m[4 + j] + m[8 + j] + m[12 + j]);
            m[j] *= r; m[4 + j] *= r; m[8 + j] *= r; m[12 + j] *= r;
        }
    }

    float4* wd = (float4*)(W_buf + (size_t)t * 16);
#pragma unroll
    for (int i = 0; i < 4; ++i)
        wd[i] = make_float4(m[i * 4 + 0] + hpost[i] * hpre[0],
                            m[i * 4 + 1] + hpost[i] * hpre[1],
                            m[i * 4 + 2] + hpost[i] * hpre[2],
                            m[i * 4 + 3] + hpost[i] * hpre[3]);
}

// ---------------- kernel 4: out[token] = W @ x[token] ----------------
__global__ void out_k(const float* __restrict__ x, float* __restrict__ out) {
    const int token = blockIdx.x;
    __shared__ float sW[16];
    if (threadIdx.x < 16) sW[threadIdx.x] = W_buf[(size_t)token * 16 + threadIdx.x];
    __syncthreads();
    const float4* xr = (const float4*)(x + (size_t)token * NC);
    float4* orow = (float4*)(out + (size_t)token * NC);
    const int c = threadIdx.x;
    float4 xv0 = xr[c], xv1 = xr[256 + c], xv2 = xr[512 + c], xv3 = xr[768 + c];
#pragma unroll
    for (int i = 0; i < 4; ++i) {
        float w0 = sW[i * 4], w1 = sW[i * 4 + 1], w2 = sW[i * 4 + 2], w3 = sW[i * 4 + 3];
        float4 o;
        o.x = w0 * xv0.x + w1 * xv1.x + w2 * xv2.x + w3 * xv3.x;
        o.y = w0 * xv0.y + w1 * xv1.y + w2 * xv2.y + w3 * xv3.y;
        o.z = w0 * xv0.z + w1 * xv1.z + w2 * xv2.z + w3 * xv3.z;
        o.w = w0 * xv0.w + w1 * xv1.w + w2 * xv2.w + w3 * xv3.w;
        orow[i * 256 + c] = o;
    }
}

// ---------------- launch ----------------
extern "C" void kernel_launch(void* const* d_in, const int* in_sizes, int n_in,
                              void* d_out, int out_size) {
    const float* x     = (const float*)d_in[0];
    const float* wnorm = (const float*)d_in[1];
    const float* ppre  = (const float*)d_in[2];
    const float* ppost = (const float*)d_in[3];
    const float* pres  = (const float*)d_in[4];
    const float* bpre  = (const float*)d_in[5];
    const float* bpost = (const float*)d_in[6];
    const float* bres  = (const float*)d_in[7];
    const float* apre  = (const float*)d_in[8];
    const float* apost = (const float*)d_in[9];
    const float* ares  = (const float*)d_in[10];
    const int*   aidx  = (const int*)d_in[11];
    float* out = (float*)d_out;

    cudaFuncSetAttribute(logits_k, cudaFuncAttributeMaxDynamicSharedMemorySize, SMEM_BYTES);

    fold_k<<<(AA * NC * 6 + 255) / 256, 256>>>(wnorm, ppre, ppost, pres, apre, apost, ares);
    logits_k<<<(BB * TT / TOK) * KSPLIT, 128, SMEM_BYTES>>>(x, aidx);
    finalize_k<<<BB * TT / 128, 128>>>(bpre, bpost, bres, aidx);
    out_k<<<BB * TT, 256>>>(x, out);
}